// round 15
// baseline (speedup 1.0000x reference)
#include <cuda_runtime.h>
#include <cuda_fp16.h>
#include <cstdint>

#define NN 50000
#define NE 800000
#define F  128
#define NBLK 196          // scan chunks of 256 covering NN

#define GRID 592          // 148 SM x 4 blocks -- co-resident guaranteed
#define NTH  (GRID * 256)

#define BM   64           // gemm rows per block
#define GT   128          // gemm threads
#define SW   132          // Hs padded row stride (floats)
#define WPAD 17           // Wpk padded nt stride (uint4s)
#define KSP  8            // k-steps of 16

// ---------------- device scratch (no allocations allowed) -------------------
// zero-initialized at module load; gemm_tc_kernel re-zeroes deg arrays +
// barrier state at its start, so every kernel_launch call sees them zeroed.
__device__ int   g_deg_out_i[NN];
__device__ int   g_deg_in_i[NN];
__device__ int   g_bar_count;
__device__ volatile int g_bar_phase;
__device__ int   g_row_start[NN];
__device__ float g_scale_out[NN];
__device__ int   g_slot[NE];
__device__ int   g_perm_src[NE + 8];
__device__ float g_h[NN * F];
__device__ uint4 g_Wpk[KSP * 32 * 16];     // fp16 frags {bh0,bh1,bl0,bl1}
__device__ int   g_block_sums[NBLK];

__device__ __forceinline__ uint32_t h2u(half2 h) {
    return *reinterpret_cast<uint32_t*>(&h);
}

// all-parallel grid barrier: monotone phase counter, no per-phase reset
__device__ __forceinline__ void grid_bar(int p) {
    __syncthreads();
    if (threadIdx.x == 0) {
        __threadfence();                          // release
        int v = atomicAdd(&g_bar_count, 1) + 1;
        if (v == GRID * p) {
            g_bar_phase = p;
        } else {
            while (g_bar_phase < p) { }
        }
    }
    __syncthreads();
    __threadfence();                              // acquire
}

__device__ __forceinline__ void fmacc(float4& acc, float c, const float4& a) {
    acc.x += c * a.x; acc.y += c * a.y; acc.z += c * a.z; acc.w += c * a.w;
}

// ---------------------------------------------------------------------------
// 1) persistent fused kernel: deg -> scan -> scatter -> agg (grid barriers)
// ---------------------------------------------------------------------------
__global__ void __launch_bounds__(256, 4)
fused_kernel(const float* __restrict__ x,
             const int* __restrict__ src, const int* __restrict__ dst,
             const float* __restrict__ weight) {
    int bid  = blockIdx.x;
    int t    = threadIdx.x;
    int gt   = bid * 256 + t;
    int lane = t & 31;
    int w    = t >> 5;

    // ---- phase A: degree histograms (grid-stride, 2 edges/iter) ----
    for (long long e0 = (long long)gt * 2; e0 < NE; e0 += (long long)NTH * 2) {
        int s0 = src[e0], s1 = src[e0 + 1];
        int d0 = dst[e0], d1 = dst[e0 + 1];
        atomicAdd(&g_deg_out_i[s0], 1);
        atomicAdd(&g_deg_out_i[s1], 1);
        g_slot[e0]     = atomicAdd(&g_deg_in_i[d0], 1);
        g_slot[e0 + 1] = atomicAdd(&g_deg_in_i[d1], 1);
    }
    // ---- W split (blocks 196..211, independent of degrees) ----
    if (bid >= NBLK && bid < NBLK + 16) {
        int i    = (bid - NBLK) * 256 + t;        // 0..4095
        int nt   = i & 15;
        int rest = i >> 4;
        int ln   = rest & 31;
        int ks   = rest >> 5;
        int tg   = ln & 3;
        int g    = ln >> 2;
        int k0 = ks * 16, n0 = nt * 8;
        float w00 = weight[(k0 + 2 * tg)     * F + n0 + g];
        float w01 = weight[(k0 + 2 * tg + 1) * F + n0 + g];
        float w10 = weight[(k0 + 2 * tg + 8) * F + n0 + g];
        float w11 = weight[(k0 + 2 * tg + 9) * F + n0 + g];
        half2 h0 = __floats2half2_rn(w00, w01);
        half2 h1 = __floats2half2_rn(w10, w11);
        half2 l0 = __floats2half2_rn(w00 - __half2float(__low2half(h0)),
                                     w01 - __half2float(__high2half(h0)));
        half2 l1 = __floats2half2_rn(w10 - __half2float(__low2half(h1)),
                                     w11 - __half2float(__high2half(h1)));
        g_Wpk[i] = make_uint4(h2u(h0), h2u(h1), h2u(l0), h2u(l1));
    }
    grid_bar(1);

    // ---- phase B1: per-chunk scan of deg_in (blocks 0..195) ----
    __shared__ int wsum[8];
    __shared__ int s_base;
    int excl = 0;
    if (bid < NBLK) {
        int gidx = bid * 256 + t;
        int v = (gidx < NN) ? g_deg_in_i[gidx] : 0;
        int xq = v;
#pragma unroll
        for (int o = 1; o < 32; o <<= 1) {
            int tt = __shfl_up_sync(0xffffffffu, xq, o);
            if (lane >= o) xq += tt;
        }
        if (lane == 31) wsum[w] = xq;
        __syncthreads();
        if (t < 8) {
            int s = wsum[t];
#pragma unroll
            for (int o = 1; o < 8; o <<= 1) {
                int tt = __shfl_up_sync(0xffu, s, o);
                if (t >= o) s += tt;
            }
            wsum[t] = s;
        }
        __syncthreads();
        int woff = (w > 0) ? wsum[w - 1] : 0;
        excl = woff + xq - v;
        if (t == 0) g_block_sums[bid] = wsum[7];
    }
    grid_bar(2);

    // ---- phase B2: add preceding chunk sums, write row_start/scale ----
    if (bid < NBLK) {
        int pv = (t < bid) ? g_block_sums[t] : 0;     // NBLK <= 256
#pragma unroll
        for (int o = 16; o > 0; o >>= 1) pv += __shfl_down_sync(0xffffffffu, pv, o);
        __syncthreads();                               // wsum reuse hazard
        if (lane == 0) wsum[w] = pv;
        __syncthreads();
        if (t == 0) {
            int s = 0;
#pragma unroll
            for (int j = 0; j < 8; j++) s += wsum[j];
            s_base = s;
        }
        __syncthreads();
        int gidx = bid * 256 + t;
        if (gidx < NN) {
            g_row_start[gidx] = excl + s_base;
            g_scale_out[gidx] = rsqrtf(fmaxf((float)g_deg_out_i[gidx], 1.0f));
        }
    }
    grid_bar(3);

    // ---- phase C: atomic-free scatter (grid-stride, 4 edges/iter) ----
    for (long long e0 = (long long)gt * 4; e0 < NE; e0 += (long long)NTH * 4) {
        int4 d  = *reinterpret_cast<const int4*>(dst + e0);
        int4 s  = *reinterpret_cast<const int4*>(src + e0);
        int4 sl = *reinterpret_cast<const int4*>(g_slot + e0);
        g_perm_src[g_row_start[d.x] + sl.x] = s.x;
        g_perm_src[g_row_start[d.y] + sl.y] = s.y;
        g_perm_src[g_row_start[d.z] + sl.z] = s.z;
        g_perm_src[g_row_start[d.w] + sl.w] = s.w;
    }
    grid_bar(4);

    // ---- phase D: CSR aggregation, warp per node (grid-stride) ----
    const float4* x4 = reinterpret_cast<const float4*>(x);
    int wid_g = gt >> 5;                 // 0..4735
    for (int node = wid_g; node < NN; node += NTH / 32) {
        int start = g_row_start[node];
        int len   = g_deg_in_i[node];
        int end   = start + len;

        float4 acc = make_float4(0.f, 0.f, 0.f, 0.f);
        int i = start;
        int head = (4 - (start & 3)) & 3;
        if (head > len) head = len;
        for (int j = 0; j < head; j++, i++) {
            int s0 = g_perm_src[i];
            fmacc(acc, g_scale_out[s0], x4[(size_t)s0 * 32 + lane]);
        }
        for (; i + 8 <= end; i += 8) {
            int4 ia = *reinterpret_cast<const int4*>(g_perm_src + i);
            int4 ib = *reinterpret_cast<const int4*>(g_perm_src + i + 4);
            float c0 = g_scale_out[ia.x], c1 = g_scale_out[ia.y];
            float c2 = g_scale_out[ia.z], c3 = g_scale_out[ia.w];
            float c4 = g_scale_out[ib.x], c5 = g_scale_out[ib.y];
            float c6 = g_scale_out[ib.z], c7 = g_scale_out[ib.w];
            float4 a0 = x4[(size_t)ia.x * 32 + lane];
            float4 a1 = x4[(size_t)ia.y * 32 + lane];
            float4 a2 = x4[(size_t)ia.z * 32 + lane];
            float4 a3 = x4[(size_t)ia.w * 32 + lane];
            float4 a4 = x4[(size_t)ib.x * 32 + lane];
            float4 a5 = x4[(size_t)ib.y * 32 + lane];
            float4 a6 = x4[(size_t)ib.z * 32 + lane];
            float4 a7 = x4[(size_t)ib.w * 32 + lane];
            fmacc(acc, c0, a0); fmacc(acc, c1, a1); fmacc(acc, c2, a2); fmacc(acc, c3, a3);
            fmacc(acc, c4, a4); fmacc(acc, c5, a5); fmacc(acc, c6, a6); fmacc(acc, c7, a7);
        }
        if (i + 4 <= end) {
            int4 ia = *reinterpret_cast<const int4*>(g_perm_src + i);
            float c0 = g_scale_out[ia.x], c1 = g_scale_out[ia.y];
            float c2 = g_scale_out[ia.z], c3 = g_scale_out[ia.w];
            float4 a0 = x4[(size_t)ia.x * 32 + lane];
            float4 a1 = x4[(size_t)ia.y * 32 + lane];
            float4 a2 = x4[(size_t)ia.z * 32 + lane];
            float4 a3 = x4[(size_t)ia.w * 32 + lane];
            fmacc(acc, c0, a0); fmacc(acc, c1, a1); fmacc(acc, c2, a2); fmacc(acc, c3, a3);
            i += 4;
        }
        for (; i < end; i++) {
            int s0 = g_perm_src[i];
            fmacc(acc, g_scale_out[s0], x4[(size_t)s0 * 32 + lane]);
        }

        float inv = rsqrtf(fmaxf((float)len, 1.0f));
        acc.x *= inv; acc.y *= inv; acc.z *= inv; acc.w *= inv;
        reinterpret_cast<float4*>(g_h + (size_t)node * F)[lane] = acc;
    }
}

// ---------------------------------------------------------------------------
// 2) GEMM via 2-way fp16-split HMMA m16n8k16 + bias; re-zeroes deg arrays
//    and barrier state for the next kernel_launch call.
// ---------------------------------------------------------------------------
__device__ __forceinline__ void mma_f16(float& d0, float& d1, float& d2, float& d3,
                                        uint32_t a0, uint32_t a1, uint32_t a2, uint32_t a3,
                                        uint32_t b0, uint32_t b1) {
    asm volatile(
        "mma.sync.aligned.m16n8k16.row.col.f32.f16.f16.f32 "
        "{%0,%1,%2,%3}, {%4,%5,%6,%7}, {%8,%9}, {%0,%1,%2,%3};"
        : "+f"(d0), "+f"(d1), "+f"(d2), "+f"(d3)
        : "r"(a0), "r"(a1), "r"(a2), "r"(a3), "r"(b0), "r"(b1));
}

__device__ __forceinline__ void split2(float2 f, uint32_t& hi, uint32_t& lo) {
    half2 h = __floats2half2_rn(f.x, f.y);
    half2 l = __floats2half2_rn(f.x - __half2float(__low2half(h)),
                                f.y - __half2float(__high2half(h)));
    hi = h2u(h); lo = h2u(l);
}

__global__ void __launch_bounds__(GT, 2)
gemm_tc_kernel(const float* __restrict__ bias, float* __restrict__ out) {
    extern __shared__ float sm[];
    uint4* Wps = reinterpret_cast<uint4*>(sm);          // KSP*32*17 uint4
    float* Hs  = sm + KSP * 32 * WPAD * 4;              // BM * SW floats
    float* Bs  = Hs + BM * SW;                          // F floats

    int tid  = threadIdx.x;
    int row0 = blockIdx.x * BM;

    // re-zero degree arrays + barrier state for the next call
    {
        int gz = blockIdx.x * GT + tid;
        if (gz < NN) { g_deg_out_i[gz] = 0; g_deg_in_i[gz] = 0; }
        if (gz == 0) { g_bar_count = 0; g_bar_phase = 0; }
    }

    for (int i = tid; i < KSP * 32 * 16; i += GT) {
        int nt = i & 15, rest = i >> 4;
        Wps[rest * WPAD + nt] = g_Wpk[i];
    }
    for (int i = tid; i < BM * (F / 4); i += GT) {
        int r = i / (F / 4), c4 = i % (F / 4);
        float4 v = make_float4(0.f, 0.f, 0.f, 0.f);
        int grow = row0 + r;
        if (grow < NN)
            v = reinterpret_cast<const float4*>(g_h)[grow * (F / 4) + c4];
        reinterpret_cast<float4*>(&Hs[r * SW + c4 * 4])[0] = v;
    }
    if (tid < F) Bs[tid] = bias[tid];
    __syncthreads();

    int warp = tid >> 5;
    int lane = tid & 31;
    int g    = lane >> 2;
    int t    = lane & 3;
    int rb   = warp * 16;

    float d[16][4];
#pragma unroll
    for (int nt = 0; nt < 16; nt++)
#pragma unroll
        for (int j = 0; j < 4; j++) d[nt][j] = 0.f;

#pragma unroll
    for (int ks = 0; ks < KSP; ks++) {
        int k0 = ks * 16;
        float2 f00 = *reinterpret_cast<float2*>(&Hs[(rb + g)     * SW + k0 + 2 * t]);
        float2 f10 = *reinterpret_cast<float2*>(&Hs[(rb + g + 8) * SW + k0 + 2 * t]);
        float2 f01 = *reinterpret_cast<float2*>(&Hs[(rb + g)     * SW + k0 + 2 * t + 8]);
        float2 f11 = *reinterpret_cast<float2*>(&Hs[(rb + g + 8) * SW + k0 + 2 * t + 8]);
        uint32_t ah0, al0, ah1, al1, ah2, al2, ah3, al3;
        split2(f00, ah0, al0);
        split2(f10, ah1, al1);
        split2(f01, ah2, al2);
        split2(f11, ah3, al3);

        const uint4* wrow = &Wps[(ks * 32 + lane) * WPAD];
#pragma unroll
        for (int nt = 0; nt < 16; nt++) {
            uint4 wb = wrow[nt];
            mma_f16(d[nt][0], d[nt][1], d[nt][2], d[nt][3],
                    ah0, ah1, ah2, ah3, wb.x, wb.y);       // Ah*Bh
            mma_f16(d[nt][0], d[nt][1], d[nt][2], d[nt][3],
                    ah0, ah1, ah2, ah3, wb.z, wb.w);       // Ah*Bl
            mma_f16(d[nt][0], d[nt][1], d[nt][2], d[nt][3],
                    al0, al1, al2, al3, wb.x, wb.y);       // Al*Bh
        }
    }

    int rA = row0 + rb + g;
    int rB = rA + 8;
#pragma unroll
    for (int nt = 0; nt < 16; nt++) {
        int col = nt * 8 + t * 2;
        float b0 = Bs[col], b1 = Bs[col + 1];
        if (rA < NN) {
            float2 o = make_float2(d[nt][0] + b0, d[nt][1] + b1);
            reinterpret_cast<float2*>(out + (size_t)rA * F + col)[0] = o;
        }
        if (rB < NN) {
            float2 o = make_float2(d[nt][2] + b0, d[nt][3] + b1);
            reinterpret_cast<float2*>(out + (size_t)rB * F + col)[0] = o;
        }
    }
}

// ---------------------------------------------------------------------------
extern "C" void kernel_launch(void* const* d_in, const int* in_sizes, int n_in,
                              void* d_out, int out_size) {
    const float* x      = (const float*)d_in[0];
    const int*   src    = (const int*)d_in[1];
    const int*   dst    = (const int*)d_in[2];
    const float* weight = (const float*)d_in[3];
    const float* bias   = (const float*)d_in[4];
    float*       out    = (float*)d_out;

    fused_kernel<<<GRID, 256>>>(x, src, dst, weight);

    int smem = (KSP * 32 * WPAD * 4 + BM * SW + F) * (int)sizeof(float); // 103936 B
    cudaFuncSetAttribute(gemm_tc_kernel, cudaFuncAttributeMaxDynamicSharedMemorySize, smem);
    gemm_tc_kernel<<<(NN + BM - 1) / BM, GT, smem>>>(bias, out);
}